// round 16
// baseline (speedup 1.0000x reference)
#include <cuda_runtime.h>
#include <cuda_fp16.h>
#include <math.h>
#include <stdint.h>

#define Nn     100000
#define Ee     1600000
#define NFEAT  512
#define NHID   256
#define NCLASS 40
#define KHOP   10
#define ALPHA  0.1f
#define NB     ((Nn + 255) / 256)   // 391 scan blocks

// ---------------- scratch (static __device__ — no allocations allowed) ----------------
__device__ __half g_hh [(size_t)Nn * NCLASS];   // h = relu(x@W1+b1)@W2+b2  [N,40] fp16
__device__ __half g_zhA[(size_t)Nn * NCLASS];   // propagation ping
__device__ __half g_zhB[(size_t)Nn * NCLASS];   // propagation pong
// W1 in mma-pair layout: [(k8*256 + n)*8 + kk*2 + h] = rna_tf32(W1[(k8*8+kk+4h)*256 + n])
__device__ float  g_W1p[(size_t)NFEAT * NHID];
// W2 in mma-pair layout: [(k8*40 + n)*8 + kk*2 + h] = rna_tf32(W2[(k8*8+kk+4h)*40 + n])
__device__ float  g_W2p[(size_t)NHID * NCLASS];
__device__ int    g_counts[Nn];
__device__ int    g_rowptr[Nn + 1];
__device__ int    g_cursor[Nn];
__device__ int    g_bsum[NB];
__device__ int    g_boff[NB + 1];
__device__ int2   g_csr[Ee];                    // {src, __float_as_int(val)}

// ---------------- helpers (sm_80+ PTX only — NO tcgen05, harness targets plain sm_103) ----------------
__device__ __forceinline__ uint32_t smem_u32(const void* p) {
  uint32_t a;
  asm("{ .reg .u64 t; cvta.to.shared.u64 t, %1; cvt.u32.u64 %0, t; }" : "=r"(a) : "l"(p));
  return a;
}
__device__ __forceinline__ uint32_t rna_tf32_bits(float x) {
  uint32_t u;
  asm("cvt.rna.tf32.f32 %0, %1;" : "=r"(u) : "f"(x));
  return u;
}
__device__ __forceinline__ void cp_async16(uint32_t dst, const void* src, uint32_t srcsz) {
  asm volatile("cp.async.cg.shared.global [%0], [%1], 16, %2;"
               :: "r"(dst), "l"(src), "r"(srcsz) : "memory");
}
__device__ __forceinline__ void mma_tf32(float d[4], const uint32_t a[4], const uint32_t b[2]) {
  asm volatile("mma.sync.aligned.m16n8k8.row.col.f32.tf32.tf32.f32 "
               "{%0,%1,%2,%3}, {%4,%5,%6,%7}, {%8,%9}, {%0,%1,%2,%3};"
               : "+f"(d[0]), "+f"(d[1]), "+f"(d[2]), "+f"(d[3])
               : "r"(a[0]), "r"(a[1]), "r"(a[2]), "r"(a[3]), "r"(b[0]), "r"(b[1]));
}

// ---------------- combined prep: W1 permute, W2 permute, zero counts ----------------
// grid = 512 (W1) + 40 (W2) + 391 (zero) = 943 blocks of 256
__global__ void prep_all_kernel(const float* __restrict__ W1, const float* __restrict__ W2) {
  int b = blockIdx.x, t = threadIdx.x;
  if (b < 512) {
    int o = b * 256 + t;
    int inner = o & 7;
    int n     = (o >> 3) & 255;
    int k8    = o >> 11;
    int kk    = inner >> 1, h = inner & 1;
    int k     = k8 * 8 + kk + h * 4;
    g_W1p[o] = __uint_as_float(rna_tf32_bits(W1[(size_t)k * NHID + n]));
  } else if (b < 552) {
    int o = (b - 512) * 256 + t;
    if (o < NHID * NCLASS) {
      int k8    = o / 320;
      int rem   = o % 320;
      int n     = rem >> 3;
      int inner = rem & 7;
      int kk    = inner >> 1, h = inner & 1;
      int k     = k8 * 8 + kk + h * 4;
      g_W2p[o] = __uint_as_float(rna_tf32_bits(W2[(size_t)k * NCLASS + n]));
    }
  } else {
    int i = (b - 552) * 256 + t;
    if (i < Nn) g_counts[i] = 0;
  }
}

// ---------------- FUSED GEMM (mma.sync tf32): g_hh = relu(x@W1+b1)@W2 + b2 ----------------
// CTA: 128 rows x full 256 cols, 512 threads = 16 warps (4M x 4N, warp tile 32x64).
// Phase 1: K-loop over NFEAT (16 stages of BK=32, cp.async double buffer).
// Phase 2: per 64-row half — stage tf32(relu(h1)) in smem, mma with W2 pairs, emit fp16.
#define SM_A0    0u
#define SM_A1    16384u
#define SM_B0    32768u
#define SM_B1    65536u
#define SM_STAGE 98304u     // 64 rows x 1024 B = 65536
#define SM_W2    163840u    // 40960 B
#define SM_TOTAL 204800

__device__ __forceinline__ void gf_load_stage(const float* __restrict__ x, int tileM,
                                              int st, uint32_t dA, uint32_t dB, int tid) {
  // A: 128 rows x 32 floats, XOR-chunk swizzle; zero-fill OOB rows
  #pragma unroll
  for (int q = 0; q < 2; q++) {
    int c = q * 512 + tid;             // 0..1023
    int m = c >> 3, ch = c & 7;
    int row = tileM + m;
    const float* src = x + (size_t)(row < Nn ? row : 0) * NFEAT + st * 32 + ch * 4;
    uint32_t dst = dA + m * 128 + ((ch ^ (m & 7)) << 4);
    cp_async16(dst, src, row < Nn ? 16u : 0u);
  }
  // B: 4 k8-chunks x 256 n x 32B pairs
  #pragma unroll
  for (int q = 0; q < 4; q++) {
    int c = q * 512 + tid;             // 0..2047
    int k8l = c >> 9, rem = c & 511, n = rem >> 1, half = rem & 1;
    const float* src = g_W1p + ((size_t)((st * 4 + k8l) * 256) + n) * 8 + half * 4;
    uint32_t dst = dB + k8l * 8192 + n * 32 + half * 16;
    cp_async16(dst, src, 16u);
  }
  asm volatile("cp.async.commit_group;" ::: "memory");
}

__device__ __forceinline__ void gf_compute_stage(uint32_t aBase, uint32_t bBase,
                                                 int wm, int wn, int g, int tig,
                                                 float acc[2][8][4]) {
  #pragma unroll
  for (int k8l = 0; k8l < 4; k8l++) {
    uint32_t bf[8][2];
    #pragma unroll
    for (int j = 0; j < 8; j++) {
      uint32_t addr = bBase + k8l * 8192 + (wn * 64 + j * 8 + g) * 32 + tig * 8;
      asm volatile("ld.shared.v2.b32 {%0,%1}, [%2];"
                   : "=r"(bf[j][0]), "=r"(bf[j][1]) : "r"(addr));
    }
    uint32_t af[2][4];
    #pragma unroll
    for (int mf = 0; mf < 2; mf++) {
      int r0 = wm * 32 + mf * 16 + g;
      int r1 = r0 + 8;
      #pragma unroll
      for (int h = 0; h < 2; h++) {
        int chunk = k8l * 2 + h;
        uint32_t ad0 = aBase + r0 * 128 + ((chunk ^ (r0 & 7)) << 4) + tig * 4;
        uint32_t ad1 = aBase + r1 * 128 + ((chunk ^ (r1 & 7)) << 4) + tig * 4;
        float f0, f1;
        asm volatile("ld.shared.f32 %0, [%1];" : "=f"(f0) : "r"(ad0));
        asm volatile("ld.shared.f32 %0, [%1];" : "=f"(f1) : "r"(ad1));
        af[mf][h * 2 + 0] = rna_tf32_bits(f0);
        af[mf][h * 2 + 1] = rna_tf32_bits(f1);
      }
    }
    #pragma unroll
    for (int mf = 0; mf < 2; mf++)
      #pragma unroll
      for (int j = 0; j < 8; j++)
        mma_tf32(acc[mf][j], af[mf], bf[j]);
  }
}

__global__ __launch_bounds__(512, 1) void gemm_fused_kernel(const float* __restrict__ x,
                                                            const float* __restrict__ b1,
                                                            const float* __restrict__ b2) {
  extern __shared__ char smem[];
  const uint32_t sb = smem_u32(smem);
  const int tid = threadIdx.x, wid = tid >> 5, lane = tid & 31;
  const int g = lane >> 2, tig = lane & 3;
  const int tileM = blockIdx.x * 128;
  const int wm = wid >> 2, wn = wid & 3;
  const uint32_t sA[2] = {sb + SM_A0, sb + SM_A1};
  const uint32_t sB[2] = {sb + SM_B0, sb + SM_B1};

  float acc[2][8][4];
  #pragma unroll
  for (int a = 0; a < 2; a++)
    #pragma unroll
    for (int b = 0; b < 8; b++)
      #pragma unroll
      for (int c = 0; c < 4; c++) acc[a][b][c] = 0.f;

  gf_load_stage(x, tileM, 0, sA[0], sB[0], tid);
  gf_load_stage(x, tileM, 1, sA[1], sB[1], tid);

  #pragma unroll 1
  for (int st = 0; st < 16; st++) {
    int buf = st & 1;
    if (st < 15) asm volatile("cp.async.wait_group 1;" ::: "memory");
    else         asm volatile("cp.async.wait_group 0;" ::: "memory");
    __syncthreads();
    gf_compute_stage(sA[buf], sB[buf], wm, wn, g, tig, acc);
    __syncthreads();
    if (st + 2 < 16) gf_load_stage(x, tileM, 2 + st, sA[buf], sB[buf], tid);
  }

  // kick W2 pair-layout load (independent smem region)
  #pragma unroll
  for (int q = 0; q < 5; q++) {
    int idx = q * 512 + tid;           // 0..2559
    cp_async16(sb + SM_W2 + idx * 16, (const char*)g_W2p + (size_t)idx * 16, 16u);
  }
  asm volatile("cp.async.commit_group;" ::: "memory");

  // ---- phase 2: two 64-row halves ----
  const uint32_t stg = sb + SM_STAGE;
  #pragma unroll 1
  for (int hf = 0; hf < 2; hf++) {
    // stage tf32(relu(h1)) for rows [hf*64, hf*64+64) — owned by warps wm in {2hf, 2hf+1}
    if ((wm >> 1) == hf) {
      #pragma unroll
      for (int j = 0; j < 8; j++) {
        int col = wn * 64 + j * 8 + tig * 2;
        float2 bv = *reinterpret_cast<const float2*>(b1 + col);
        int ch = col >> 2, ip = (col & 3) * 4;
        #pragma unroll
        for (int mf = 0; mf < 2; mf++) {
          int rr0 = (wm & 1) * 32 + mf * 16 + g;   // 0..63 within half
          int rr1 = rr0 + 8;
          uint32_t v0 = rna_tf32_bits(fmaxf(acc[mf][j][0] + bv.x, 0.f));
          uint32_t v1 = rna_tf32_bits(fmaxf(acc[mf][j][1] + bv.y, 0.f));
          uint32_t v2 = rna_tf32_bits(fmaxf(acc[mf][j][2] + bv.x, 0.f));
          uint32_t v3 = rna_tf32_bits(fmaxf(acc[mf][j][3] + bv.y, 0.f));
          uint32_t a0 = stg + rr0 * 1024 + ((ch ^ (rr0 & 7)) << 4) + ip;
          uint32_t a1 = stg + rr1 * 1024 + ((ch ^ (rr1 & 7)) << 4) + ip;
          asm volatile("st.shared.v2.b32 [%0], {%1,%2};" :: "r"(a0), "r"(v0), "r"(v1) : "memory");
          asm volatile("st.shared.v2.b32 [%0], {%1,%2};" :: "r"(a1), "r"(v2), "r"(v3) : "memory");
        }
      }
    }
    if (hf == 0) asm volatile("cp.async.wait_group 0;" ::: "memory");  // W2 ready
    __syncthreads();

    // compute h tile 64x40: 20 warp-tiles (mg 0..3 x ng 0..4) over 16 warps
    #pragma unroll
    for (int pass = 0; pass < 2; pass++) {
      int wt = wid + pass * 16;
      if (wt < 20) {
        int mg = wt & 3, ng = wt >> 2;
        float a2[4] = {0.f, 0.f, 0.f, 0.f};
        int rr0 = mg * 16 + g, rr1 = rr0 + 8;
        uint32_t rbase0 = stg + rr0 * 1024 + tig * 4;
        uint32_t rbase1 = stg + rr1 * 1024 + tig * 4;
        uint32_t wbase  = sb + SM_W2 + (ng * 8 + g) * 32 + tig * 8;
        #pragma unroll
        for (int k8 = 0; k8 < 32; k8++) {
          uint32_t af[4];
          int c0 = k8 * 2, c1 = c0 + 1;
          asm volatile("ld.shared.b32 %0, [%1];" : "=r"(af[0]) : "r"(rbase0 + ((c0 ^ (rr0 & 7)) << 4)));
          asm volatile("ld.shared.b32 %0, [%1];" : "=r"(af[1]) : "r"(rbase1 + ((c0 ^ (rr1 & 7)) << 4)));
          asm volatile("ld.shared.b32 %0, [%1];" : "=r"(af[2]) : "r"(rbase0 + ((c1 ^ (rr0 & 7)) << 4)));
          asm volatile("ld.shared.b32 %0, [%1];" : "=r"(af[3]) : "r"(rbase1 + ((c1 ^ (rr1 & 7)) << 4)));
          uint32_t bf[2];
          asm volatile("ld.shared.v2.b32 {%0,%1}, [%2];"
                       : "=r"(bf[0]), "=r"(bf[1]) : "r"(wbase + k8 * 1280));
          mma_tf32(a2, af, bf);
        }
        int col = ng * 8 + tig * 2;
        float2 bv = *reinterpret_cast<const float2*>(b2 + col);
        int row0 = tileM + hf * 64 + mg * 16 + g, row1 = row0 + 8;
        if (row0 < Nn)
          *reinterpret_cast<__half2*>(&g_hh[(size_t)row0 * NCLASS + col]) =
              __floats2half2_rn(a2[0] + bv.x, a2[1] + bv.y);
        if (row1 < Nn)
          *reinterpret_cast<__half2*>(&g_hh[(size_t)row1 * NCLASS + col]) =
              __floats2half2_rn(a2[2] + bv.x, a2[3] + bv.y);
      }
    }
    __syncthreads();   // staging reused by next half
  }
}

// ---------------- CSR build (by dst) ----------------
__global__ void hist_kernel(const int* __restrict__ edst) {
  int e = blockIdx.x * blockDim.x + threadIdx.x;
  if (e < Ee) atomicAdd(&g_counts[edst[e]], 1);
}

__global__ __launch_bounds__(256) void scan1_kernel() {
  __shared__ int sh[256];
  int t = threadIdx.x, i = blockIdx.x * 256 + t;
  int v = (i < Nn) ? g_counts[i] : 0;
  sh[t] = v;
  __syncthreads();
  #pragma unroll
  for (int off = 1; off < 256; off <<= 1) {
    int tv = (t >= off) ? sh[t - off] : 0;
    __syncthreads();
    sh[t] += tv;
    __syncthreads();
  }
  if (i < Nn) g_rowptr[i] = sh[t] - v;
  if (t == 255) g_bsum[blockIdx.x] = sh[255];
}

__global__ __launch_bounds__(512) void scan2_kernel() {
  __shared__ int sh[512];
  int t = threadIdx.x;
  int v = (t < NB) ? g_bsum[t] : 0;
  sh[t] = v;
  __syncthreads();
  #pragma unroll
  for (int off = 1; off < 512; off <<= 1) {
    int tv = (t >= off) ? sh[t - off] : 0;
    __syncthreads();
    sh[t] += tv;
    __syncthreads();
  }
  if (t < NB) g_boff[t] = sh[t] - v;
  if (t == NB - 1) g_boff[NB] = sh[t];
}

__global__ __launch_bounds__(256) void scan3_kernel() {
  int i = blockIdx.x * 256 + threadIdx.x;
  if (i < Nn) {
    int r = g_rowptr[i] + g_boff[blockIdx.x];
    g_rowptr[i] = r;
    g_cursor[i] = r;
  }
  if (i == 0) g_rowptr[Nn] = g_boff[NB];
}

__global__ void scatter_kernel(const int* __restrict__ esrc, const int* __restrict__ edst,
                               const float* __restrict__ eval) {
  int e = blockIdx.x * blockDim.x + threadIdx.x;
  if (e < Ee) {
    int d = edst[e];
    int p = atomicAdd(&g_cursor[d], 1);
    g_csr[p] = make_int2(esrc[e], __float_as_int(eval[e]));
  }
}

// ---------------- APPNP propagation (z fp16) + fused final log_softmax ----------------
// Warp per dst row, 3 edge-groups x 10 lanes; each lane gathers 4 classes (uint2).
// Last iteration computes log_softmax in-warp and writes fp32 d_out directly.
__global__ __launch_bounds__(256) void spmm_kernel(int it, float* __restrict__ out) {
  const __half* zin  = (it == 0) ? g_hh : ((it & 1) ? g_zhA : g_zhB);
  __half*       zout = (it & 1) ? g_zhB : g_zhA;
  int warp = threadIdx.x >> 5, lane = threadIdx.x & 31;
  int row = blockIdx.x * 8 + warp;
  if (row >= Nn) return;
  int s = g_rowptr[row], e = g_rowptr[row + 1];
  int grp = lane / 10, li = lane % 10;      // grp 3 = lanes 30,31 inactive
  bool act = grp < 3;
  float a0 = 0.f, a1 = 0.f, a2 = 0.f, a3 = 0.f;
  int i = s;
  for (; i + 3 <= e; i += 3) {
    if (act) {
      int2 pv = g_csr[i + grp];
      float v = __int_as_float(pv.y);
      uint2 zb = *reinterpret_cast<const uint2*>(zin + (size_t)pv.x * NCLASS + li * 4);
      float2 f0 = __half22float2(*reinterpret_cast<__half2*>(&zb.x));
      float2 f1 = __half22float2(*reinterpret_cast<__half2*>(&zb.y));
      a0 += v * f0.x; a1 += v * f0.y; a2 += v * f1.x; a3 += v * f1.y;
    }
  }
  if (act && i + grp < e) {
    int2 pv = g_csr[i + grp];
    float v = __int_as_float(pv.y);
    uint2 zb = *reinterpret_cast<const uint2*>(zin + (size_t)pv.x * NCLASS + li * 4);
    float2 f0 = __half22float2(*reinterpret_cast<__half2*>(&zb.x));
    float2 f1 = __half22float2(*reinterpret_cast<__half2*>(&zb.y));
    a0 += v * f0.x; a1 += v * f0.y; a2 += v * f1.x; a3 += v * f1.y;
  }
  // cross-group reduction: lanes 0..9 gather partials from +10, +20
  float t0 = __shfl_sync(0xffffffffu, a0, lane + 10), u0 = __shfl_sync(0xffffffffu, a0, lane + 20);
  float t1 = __shfl_sync(0xffffffffu, a1, lane + 10), u1 = __shfl_sync(0xffffffffu, a1, lane + 20);
  float t2 = __shfl_sync(0xffffffffu, a2, lane + 10), u2 = __shfl_sync(0xffffffffu, a2, lane + 20);
  float t3 = __shfl_sync(0xffffffffu, a3, lane + 10), u3 = __shfl_sync(0xffffffffu, a3, lane + 20);
  a0 += t0 + u0; a1 += t1 + u1; a2 += t2 + u2; a3 += t3 + u3;

  float o0 = 0.f, o1 = 0.f, o2 = 0.f, o3 = 0.f;
  bool lead = lane < 10;
  if (lead) {
    uint2 hb = *reinterpret_cast<const uint2*>(g_hh + (size_t)row * NCLASS + lane * 4);
    float2 h0 = __half22float2(*reinterpret_cast<__half2*>(&hb.x));
    float2 h1 = __half22float2(*reinterpret_cast<__half2*>(&hb.y));
    o0 = (1.f - ALPHA) * a0 + ALPHA * h0.x;
    o1 = (1.f - ALPHA) * a1 + ALPHA * h0.y;
    o2 = (1.f - ALPHA) * a2 + ALPHA * h1.x;
    o3 = (1.f - ALPHA) * a3 + ALPHA * h1.y;
  }

  if (it != KHOP - 1) {
    if (lead) {
      uint2 ob;
      __half2 olo = __floats2half2_rn(o0, o1), ohi = __floats2half2_rn(o2, o3);
      ob.x = *reinterpret_cast<uint32_t*>(&olo);
      ob.y = *reinterpret_cast<uint32_t*>(&ohi);
      *reinterpret_cast<uint2*>(zout + (size_t)row * NCLASS + lane * 4) = ob;
    }
  } else {
    // fused log_softmax over the 40 classes spread across lanes 0..9 (width-16 xor tree)
    float m = lead ? fmaxf(fmaxf(o0, o1), fmaxf(o2, o3)) : -1e30f;
    #pragma unroll
    for (int off = 8; off > 0; off >>= 1)
      m = fmaxf(m, __shfl_xor_sync(0xffffffffu, m, off, 16));
    float sum = lead ? (expf(o0 - m) + expf(o1 - m) + expf(o2 - m) + expf(o3 - m)) : 0.f;
    #pragma unroll
    for (int off = 8; off > 0; off >>= 1)
      sum += __shfl_xor_sync(0xffffffffu, sum, off, 16);
    if (lead) {
      float ls = m + logf(sum);
      *reinterpret_cast<float4*>(out + (size_t)row * NCLASS + lane * 4) =
          make_float4(o0 - ls, o1 - ls, o2 - ls, o3 - ls);
    }
  }
}

// ---------------- launch ----------------
extern "C" void kernel_launch(void* const* d_in, const int* in_sizes, int n_in,
                              void* d_out, int out_size) {
  const float* x    = (const float*)d_in[0];
  const int*   esrc = (const int*)  d_in[1];
  const int*   edst = (const int*)  d_in[2];
  const float* ev   = (const float*)d_in[3];
  const float* W1   = (const float*)d_in[4];
  const float* b1   = (const float*)d_in[5];
  const float* W2   = (const float*)d_in[6];
  const float* b2   = (const float*)d_in[7];
  float* out = (float*)d_out;

  cudaFuncSetAttribute(gemm_fused_kernel, cudaFuncAttributeMaxDynamicSharedMemorySize, SM_TOTAL);

  prep_all_kernel<<<943, 256>>>(W1, W2);
  gemm_fused_kernel<<<(Nn + 127) / 128, 512, SM_TOTAL>>>(x, b1, b2);

  hist_kernel<<<(Ee + 255) / 256, 256>>>(edst);
  scan1_kernel<<<NB, 256>>>();
  scan2_kernel<<<1, 512>>>();
  scan3_kernel<<<NB, 256>>>();
  scatter_kernel<<<(Ee + 255) / 256, 256>>>(esrc, edst, ev);

  for (int it = 0; it < KHOP; it++)
    spmm_kernel<<<(Nn + 7) / 8, 256>>>(it, out);
}